// round 1
// baseline (speedup 1.0000x reference)
#include <cuda_runtime.h>
#include <cuda_bf16.h>

// Problem constants
#define T_STEPS 16384
#define D_IN    512
#define H_DIM   1024
#define O_DIM   512

// Recurrence kernel config: 64 CTAs x 512 threads (16 warps).
// warp -> one output row; lane holds W[row][lane + 32k], k=0..31.
#define NCTA     64
#define NTHREADS 512
#define WARPS    16

// 64 MB scratch for all hidden states (also the inter-CTA h exchange buffer).
__device__ float    g_hs[T_STEPS * H_DIM];
__device__ unsigned g_count;

__global__ void init_kernel() { g_count = 0u; }

__global__ __launch_bounds__(NTHREADS, 1)
void rnn_kernel(const int* __restrict__ inputs,
                const float* __restrict__ h0,
                const float* __restrict__ U,
                const float* __restrict__ W,
                const float* __restrict__ bh,
                float* __restrict__ out_hT)
{
    extern __shared__ int sIn[];   // all T inputs: 64 KB
    const int tid  = threadIdx.x;
    const int lane = tid & 31;
    const int warp = tid >> 5;
    const int row  = blockIdx.x * WARPS + warp;

    // Stage the token sequence in smem (coalesced, once).
    for (int i = tid; i < T_STEPS; i += NTHREADS) sIn[i] = inputs[i];

    // Register-resident W slice: w[k] = W[row][k*32 + lane]  (coalesced per k)
    float w[32];
    const float* Wrow = W + (size_t)row * H_DIM;
#pragma unroll
    for (int k = 0; k < 32; k++) w[k] = Wrow[k * 32 + lane];

    const float bias = bh[row];
    const float* Urow = U + (size_t)row * D_IN;

    __syncthreads();

    // Prefetch ux for t=0 (uniform across lanes -> single sector)
    float ux = Urow[sIn[0]];

    volatile unsigned* cnt = &g_count;

    for (int t = 0; t < T_STEPS; t++) {
        // Prefetch next step's U gather early so L2 latency hides under the dot.
        float ux_next = 0.f;
        if (t + 1 < T_STEPS) ux_next = Urow[sIn[t + 1]];

        const float* hp = (t == 0) ? h0 : (g_hs + (size_t)(t - 1) * H_DIM);

        // Partial dot: 32 coalesced L2 loads + 4 FMA chains.
        float a0 = 0.f, a1 = 0.f, a2 = 0.f, a3 = 0.f;
#pragma unroll
        for (int k = 0; k < 32; k += 4) {
            a0 += w[k + 0] * hp[(k + 0) * 32 + lane];
            a1 += w[k + 1] * hp[(k + 1) * 32 + lane];
            a2 += w[k + 2] * hp[(k + 2) * 32 + lane];
            a3 += w[k + 3] * hp[(k + 3) * 32 + lane];
        }
        float acc = (a0 + a1) + (a2 + a3);

        // Warp tree-reduce
        acc += __shfl_xor_sync(0xffffffffu, acc, 16);
        acc += __shfl_xor_sync(0xffffffffu, acc, 8);
        acc += __shfl_xor_sync(0xffffffffu, acc, 4);
        acc += __shfl_xor_sync(0xffffffffu, acc, 2);
        acc += __shfl_xor_sync(0xffffffffu, acc, 1);

        if (lane == 0) {
            float hv = tanhf(acc + ux + bias);
            g_hs[(size_t)t * H_DIM + row] = hv;
        }
        ux = ux_next;

        // Grid barrier: release (fence + RED) / acquire (poll + fence).
        __syncthreads();
        if (tid == 0) {
            __threadfence();                 // make this CTA's h writes visible
            atomicAdd(&g_count, 1u);         // emitted as RED.GLOBAL (no return use)
            const unsigned target = (unsigned)(t + 1) * NCTA;
            while (*cnt < target) { }        // L2-hit poll
            __threadfence();                 // acquire
        }
        __syncthreads();
    }

    // h_T output (all writes globally visible after final barrier)
    if (blockIdx.x == 0) {
        for (int i = tid; i < H_DIM; i += NTHREADS)
            out_hT[i] = g_hs[(size_t)(T_STEPS - 1) * H_DIM + i];
    }
}

// ---------------------------------------------------------------------------
// logits = hs @ V^T + by   :  C[16384 x 512] = A[16384 x 1024] * V^T
// Tiled fp32 SIMT GEMM: 64x64x16 tiles, 256 threads, 4x4 register tiles.
// ---------------------------------------------------------------------------
#define BM 64
#define BN 64
#define BK 16

__global__ __launch_bounds__(256)
void gemm_kernel(const float* __restrict__ A,
                 const float* __restrict__ V,
                 const float* __restrict__ by,
                 float* __restrict__ C)
{
    __shared__ float As[BK][BM + 4];
    __shared__ float Bs[BK][BN + 4];

    const int tid = threadIdx.x;
    const int bm  = blockIdx.y * BM;   // T dimension
    const int bn  = blockIdx.x * BN;   // O dimension
    const int tx  = tid & 15;          // 0..15 -> 4 cols each
    const int ty  = tid >> 4;          // 0..15 -> 4 rows each

    const int lr = tid >> 2;           // 0..63 tile row for loads
    const int lk = (tid & 3) * 4;      // 0,4,8,12 k-offset for loads

    float acc[4][4];
#pragma unroll
    for (int i = 0; i < 4; i++)
#pragma unroll
        for (int j = 0; j < 4; j++) acc[i][j] = 0.f;

    for (int kt = 0; kt < H_DIM; kt += BK) {
        // A tile (transposed into smem): As[k][m]
        float4 av = *(const float4*)&A[(size_t)(bm + lr) * H_DIM + kt + lk];
        As[lk + 0][lr] = av.x; As[lk + 1][lr] = av.y;
        As[lk + 2][lr] = av.z; As[lk + 3][lr] = av.w;
        // B tile: Bs[k][n] = V[n][k]
        float4 bv = *(const float4*)&V[(size_t)(bn + lr) * H_DIM + kt + lk];
        Bs[lk + 0][lr] = bv.x; Bs[lk + 1][lr] = bv.y;
        Bs[lk + 2][lr] = bv.z; Bs[lk + 3][lr] = bv.w;
        __syncthreads();

#pragma unroll
        for (int k = 0; k < BK; k++) {
            float4 ra = *(const float4*)&As[k][ty * 4];
            float4 rb = *(const float4*)&Bs[k][tx * 4];
            float raa[4] = {ra.x, ra.y, ra.z, ra.w};
            float rbb[4] = {rb.x, rb.y, rb.z, rb.w};
#pragma unroll
            for (int i = 0; i < 4; i++)
#pragma unroll
                for (int j = 0; j < 4; j++)
                    acc[i][j] += raa[i] * rbb[j];
        }
        __syncthreads();
    }

    const float4 byv = *(const float4*)&by[bn + tx * 4];
    const float bb[4] = {byv.x, byv.y, byv.z, byv.w};
#pragma unroll
    for (int i = 0; i < 4; i++) {
        float4 o;
        o.x = acc[i][0] + bb[0];
        o.y = acc[i][1] + bb[1];
        o.z = acc[i][2] + bb[2];
        o.w = acc[i][3] + bb[3];
        *(float4*)&C[(size_t)(bm + ty * 4 + i) * O_DIM + bn + tx * 4] = o;
    }
}

extern "C" void kernel_launch(void* const* d_in, const int* in_sizes, int n_in,
                              void* d_out, int out_size)
{
    (void)in_sizes; (void)n_in; (void)out_size;
    const int*   inputs = (const int*)  d_in[0];
    const float* h0     = (const float*)d_in[1];
    const float* U      = (const float*)d_in[2];
    const float* W      = (const float*)d_in[3];
    const float* V      = (const float*)d_in[4];
    const float* bh     = (const float*)d_in[5];
    const float* by     = (const float*)d_in[6];

    float* logits = (float*)d_out;                         // T*O
    float* out_hT = (float*)d_out + (size_t)T_STEPS * O_DIM; // + H

    // 64 KB dynamic smem for the token sequence.
    cudaFuncSetAttribute(rnn_kernel,
                         cudaFuncAttributeMaxDynamicSharedMemorySize,
                         T_STEPS * (int)sizeof(int));

    init_kernel<<<1, 1>>>();
    rnn_kernel<<<NCTA, NTHREADS, T_STEPS * sizeof(int)>>>(inputs, h0, U, W, bh, out_hT);

    // hs is in g_hs; read its device address host-side is not needed —
    // pass via a small launch using the symbol through a helper kernel is
    // unnecessary: we can get the address with cudaGetSymbolAddress (not an
    // allocation, graph-safe).
    static float* hs_ptr = nullptr;
    if (!hs_ptr) { void* p = nullptr; cudaGetSymbolAddress(&p, g_hs); hs_ptr = (float*)p; }

    dim3 ggrid(O_DIM / BN, T_STEPS / BM);
    gemm_kernel<<<ggrid, 256>>>(hs_ptr, V, by, logits);
}

// round 2
// speedup vs baseline: 1.2330x; 1.2330x over previous
#include <cuda_runtime.h>
#include <cuda_bf16.h>

// Problem constants
#define T_STEPS 16384
#define D_IN    512
#define H_DIM   1024
#define O_DIM   512

// Recurrence: 64 CTAs x 256 threads (8 warps), 2 rows per warp -> 16 rows/CTA.
// Each thread holds W[row][j*128 + lane*4 + c] for j=0..7, c=0..3 (32 cols) x 2 rows.
#define NCTA     64
#define NTHREADS 256
#define WARPS    8

__device__ float    g_hs[T_STEPS * H_DIM];  // full hidden-state history (exchange + GEMM input)
__device__ unsigned g_count;                 // step barrier counter (zero-init, self-resetting)
__device__ unsigned g_done;                  // exit barrier counter

__device__ __forceinline__ float fast_tanh(float x) {
    float e = __expf(2.0f * x);              // inf for large x, 0 for very negative -> correct limits
    return 1.0f - __fdividef(2.0f, e + 1.0f);
}

__global__ __launch_bounds__(NTHREADS, 1)
void rnn_kernel(const int* __restrict__ inputs,
                const float* __restrict__ h0,
                const float* __restrict__ U,
                const float* __restrict__ W,
                const float* __restrict__ bh,
                float* __restrict__ out_hT)
{
    extern __shared__ int sIn[];             // 16384 tokens: 64 KB
    __shared__ float hs_s[H_DIM];            // staged previous hidden state: 4 KB

    const int tid  = threadIdx.x;
    const int lane = tid & 31;
    const int warp = tid >> 5;
    const int rowbase = blockIdx.x * 16 + warp * 2;   // this warp's 2 rows

    // Stage token sequence
    for (int i = tid; i < T_STEPS; i += NTHREADS) sIn[i] = inputs[i];

    // Register-resident W slices for 2 rows (float4 coalesced loads)
    float w0[32], w1[32];
    {
        const float* W0 = W + (size_t)rowbase * H_DIM;
        const float* W1 = W + (size_t)(rowbase + 1) * H_DIM;
#pragma unroll
        for (int j = 0; j < 8; j++) {
            float4 a = *(const float4*)&W0[j * 128 + lane * 4];
            w0[j*4+0] = a.x; w0[j*4+1] = a.y; w0[j*4+2] = a.z; w0[j*4+3] = a.w;
            float4 b = *(const float4*)&W1[j * 128 + lane * 4];
            w1[j*4+0] = b.x; w1[j*4+1] = b.y; w1[j*4+2] = b.z; w1[j*4+3] = b.w;
        }
    }

    // Per-lane row constants (lanes 0 and 1 own rows rowbase+0 / rowbase+1)
    const int myrow = rowbase + lane;        // valid for lane < 2
    float bias = 0.0f, ux = 0.0f;
    __syncthreads();                         // sIn ready
    if (lane < 2) {
        bias = bh[myrow];
        ux = U[(size_t)myrow * D_IN + sIn[0]];
    }

    for (int t = 0; t < T_STEPS; t++) {
        // Stage h_{t-1} into smem (256 threads x float4 = 1024 floats)
        const float* hprev = (t == 0) ? h0 : (g_hs + (size_t)(t - 1) * H_DIM);
        float4 hv4 = *(const float4*)&hprev[tid * 4];
        *(float4*)&hs_s[tid * 4] = hv4;

        // Prefetch next ux (L2 hit on U) while staging completes
        float ux_next = 0.0f;
        if (lane < 2 && t + 1 < T_STEPS)
            ux_next = U[(size_t)myrow * D_IN + sIn[t + 1]];

        __syncthreads();                     // hs_s ready

        // Dot products: 2 rows, 2 accumulator chains each
        float a00 = 0.f, a01 = 0.f, a10 = 0.f, a11 = 0.f;
#pragma unroll
        for (int j = 0; j < 8; j++) {
            float4 hv = *(const float4*)&hs_s[j * 128 + lane * 4];
            a00 += w0[j*4+0] * hv.x;  a01 += w0[j*4+1] * hv.y;
            a00 += w0[j*4+2] * hv.z;  a01 += w0[j*4+3] * hv.w;
            a10 += w1[j*4+0] * hv.x;  a11 += w1[j*4+1] * hv.y;
            a10 += w1[j*4+2] * hv.z;  a11 += w1[j*4+3] * hv.w;
        }
        float r0 = a00 + a01;
        float r1 = a10 + a11;

        // Two interleaved butterfly reductions (latencies overlap)
#pragma unroll
        for (int s = 16; s > 0; s >>= 1) {
            r0 += __shfl_xor_sync(0xffffffffu, r0, s);
            r1 += __shfl_xor_sync(0xffffffffu, r1, s);
        }

        if (lane < 2) {
            float pre = ((lane == 0) ? r0 : r1) + ux + bias;
            g_hs[(size_t)t * H_DIM + myrow] = fast_tanh(pre);
        }
        ux = ux_next;

        if (t < T_STEPS - 1) {
            __syncthreads();                 // all rows written; also protects hs_s reuse
            if (tid == 0) {
                asm volatile("red.release.gpu.global.add.u32 [%0], %1;"
                             :: "l"(&g_count), "r"(1u) : "memory");
                const unsigned target = (unsigned)(t + 1) * NCTA;
                unsigned v;
                do {
                    asm volatile("ld.acquire.gpu.global.u32 %0, [%1];"
                                 : "=r"(v) : "l"(&g_count) : "memory");
                } while (v < target);
            }
            __syncthreads();                 // release workers
        }
    }

    // Exit: separate done-counter so g_count can be safely reset for the next replay
    __syncthreads();
    if (tid == 0) {
        asm volatile("red.release.gpu.global.add.u32 [%0], %1;"
                     :: "l"(&g_done), "r"(1u) : "memory");
    }
    if (blockIdx.x == 0) {
        if (tid == 0) {
            unsigned v;
            do {
                asm volatile("ld.acquire.gpu.global.u32 %0, [%1];"
                             : "=r"(v) : "l"(&g_done) : "memory");
            } while (v < NCTA);
            g_count = 0u;                    // no CTA reads these anymore
            g_done  = 0u;
        }
        __syncthreads();
        for (int i = tid; i < H_DIM; i += NTHREADS)
            out_hT[i] = g_hs[(size_t)(T_STEPS - 1) * H_DIM + i];
    }
}

// ---------------------------------------------------------------------------
// logits = hs @ V^T + by : C[16384 x 512] = A[16384 x 1024] * V[512 x 1024]^T
// 128x64x16 tiles, 256 threads, 8x4 register microtiles.
// ---------------------------------------------------------------------------
#define BM 128
#define BN 64
#define BK 16

__global__ __launch_bounds__(256)
void gemm_kernel(const float* __restrict__ A,
                 const float* __restrict__ V,
                 const float* __restrict__ by,
                 float* __restrict__ C)
{
    __shared__ float As[BK][BM + 4];   // [k][m]
    __shared__ float Bs[BK][BN + 4];   // [k][n]

    const int tid = threadIdx.x;
    const int bm  = blockIdx.y * BM;
    const int bn  = blockIdx.x * BN;
    const int tx  = tid & 15;          // 0..15 -> 4 output cols
    const int ty  = tid >> 4;          // 0..15 -> 8 output rows

    const int ar = tid >> 1;           // 0..127
    const int ak = (tid & 1) * 8;      // 0 or 8
    const int br = tid >> 2;           // 0..63
    const int bk = (tid & 3) * 4;      // 0,4,8,12

    float acc[8][4];
#pragma unroll
    for (int i = 0; i < 8; i++)
#pragma unroll
        for (int j = 0; j < 4; j++) acc[i][j] = 0.f;

    for (int kt = 0; kt < H_DIM; kt += BK) {
        float4 a0 = *(const float4*)&A[(size_t)(bm + ar) * H_DIM + kt + ak];
        float4 a1 = *(const float4*)&A[(size_t)(bm + ar) * H_DIM + kt + ak + 4];
        float4 bv = *(const float4*)&V[(size_t)(bn + br) * H_DIM + kt + bk];
        As[ak + 0][ar] = a0.x; As[ak + 1][ar] = a0.y;
        As[ak + 2][ar] = a0.z; As[ak + 3][ar] = a0.w;
        As[ak + 4][ar] = a1.x; As[ak + 5][ar] = a1.y;
        As[ak + 6][ar] = a1.z; As[ak + 7][ar] = a1.w;
        Bs[bk + 0][br] = bv.x; Bs[bk + 1][br] = bv.y;
        Bs[bk + 2][br] = bv.z; Bs[bk + 3][br] = bv.w;
        __syncthreads();

#pragma unroll
        for (int k = 0; k < BK; k++) {
            float4 rb = *(const float4*)&Bs[k][tx * 4];
            float4 ra0 = *(const float4*)&As[k][ty * 8];
            float4 ra1 = *(const float4*)&As[k][ty * 8 + 4];
            float ra[8] = {ra0.x, ra0.y, ra0.z, ra0.w, ra1.x, ra1.y, ra1.z, ra1.w};
            float rbb[4] = {rb.x, rb.y, rb.z, rb.w};
#pragma unroll
            for (int i = 0; i < 8; i++)
#pragma unroll
                for (int j = 0; j < 4; j++)
                    acc[i][j] += ra[i] * rbb[j];
        }
        __syncthreads();
    }

    const float4 byv = *(const float4*)&by[bn + tx * 4];
    const float bb[4] = {byv.x, byv.y, byv.z, byv.w};
#pragma unroll
    for (int i = 0; i < 8; i++) {
        float4 o;
        o.x = acc[i][0] + bb[0];
        o.y = acc[i][1] + bb[1];
        o.z = acc[i][2] + bb[2];
        o.w = acc[i][3] + bb[3];
        *(float4*)&C[(size_t)(bm + ty * 8 + i) * O_DIM + bn + tx * 4] = o;
    }
}

extern "C" void kernel_launch(void* const* d_in, const int* in_sizes, int n_in,
                              void* d_out, int out_size)
{
    (void)in_sizes; (void)n_in; (void)out_size;
    const int*   inputs = (const int*)  d_in[0];
    const float* h0     = (const float*)d_in[1];
    const float* U      = (const float*)d_in[2];
    const float* W      = (const float*)d_in[3];
    const float* V      = (const float*)d_in[4];
    const float* bh     = (const float*)d_in[5];
    const float* by     = (const float*)d_in[6];

    float* logits = (float*)d_out;                           // T*O
    float* out_hT = (float*)d_out + (size_t)T_STEPS * O_DIM; // + H

    cudaFuncSetAttribute(rnn_kernel,
                         cudaFuncAttributeMaxDynamicSharedMemorySize,
                         T_STEPS * (int)sizeof(int));

    rnn_kernel<<<NCTA, NTHREADS, T_STEPS * sizeof(int)>>>(inputs, h0, U, W, bh, out_hT);

    static float* hs_ptr = nullptr;
    if (!hs_ptr) { void* p = nullptr; cudaGetSymbolAddress(&p, g_hs); hs_ptr = (float*)p; }

    dim3 ggrid(O_DIM / BN, T_STEPS / BM);
    gemm_kernel<<<ggrid, 256>>>(hs_ptr, V, by, logits);
}